// round 3
// baseline (speedup 1.0000x reference)
#include <cuda_runtime.h>
#include <cuda_fp16.h>
#include <cstdint>
#include <cstddef>

// ---------------- problem constants ----------------
#define B_   8
#define T_   12
#define P_   1000
#define N_   20000
#define E_   60000
#define FP_  32
#define FN_  32
#define H_   12
#define K_   768                 // IN_DIM == HID
#define M_   (B_ * N_)           // 160000 rows

// ---------------- device scratch (static; no allocs allowed) ----------------
__device__ __half g_X[(size_t)M_ * K_];     // fp16 GEMM input, [b*N+n][768] = [nx(384) | pxn(384)]
__device__ __half g_W1t[K_ * K_];           // W1 transposed, K-major: W1t[h][d]
__device__ int    g_cnt[N_];
__device__ int    g_off[N_ + 1];
__device__ int    g_pos[N_];
__device__ int    g_edgep[E_];              // patch index p per edge, CSR-sorted by node

// ---------------- small prep kernels ----------------
__global__ void k_zero_cnt() {
    int i = blockIdx.x * blockDim.x + threadIdx.x;
    if (i < N_) g_cnt[i] = 0;
}

__global__ void k_hist(const int* __restrict__ mapper) {
    int e = blockIdx.x * blockDim.x + threadIdx.x;
    if (e < E_) atomicAdd(&g_cnt[mapper[e]], 1);
}

__global__ void k_scan() {
    __shared__ int buf[1024];
    __shared__ int carry;
    int t = threadIdx.x;
    if (t == 0) { carry = 0; g_off[0] = 0; }
    __syncthreads();
    for (int base = 0; base < N_; base += 1024) {
        int i = base + t;
        int v = (i < N_) ? g_cnt[i] : 0;
        buf[t] = v;
        __syncthreads();
        for (int s = 1; s < 1024; s <<= 1) {
            int add = (t >= s) ? buf[t - s] : 0;
            __syncthreads();
            buf[t] += add;
            __syncthreads();
        }
        int incl = buf[t] + carry;
        if (i < N_) { g_off[i + 1] = incl; g_pos[i] = incl - v; }
        __syncthreads();
        if (t == 1023) carry = incl;
        __syncthreads();
    }
}

__global__ void k_scatter(const int* __restrict__ mapper, const int* __restrict__ batch) {
    int e = blockIdx.x * blockDim.x + threadIdx.x;
    if (e < E_) {
        int n = mapper[e];
        int idx = atomicAdd(&g_pos[n], 1);
        g_edgep[idx] = batch[e];
    }
}

// W1 (d,h) row-major -> W1t (h,d) fp16 K-major for MMA B operand
__global__ void k_w1t(const float* __restrict__ W1) {
    int i = blockIdx.x * blockDim.x + threadIdx.x;
    if (i < K_ * K_) {
        int k = i / K_, h = i % K_;
        g_W1t[h * K_ + k] = __float2half_rn(W1[i]);
    }
}

// nodes_x (B,T,N,32) -> X[b*N+n][t*32+fn] fp16
__global__ void k_nx(const float* __restrict__ nodes_x) {
    int i = blockIdx.x * blockDim.x + threadIdx.x;   // B*T*N*4 threads, 8 floats each
    if (i >= B_ * T_ * N_ * 4) return;
    int q  = i & 3;
    int n  = (i >> 2) % N_;
    int bt = (i >> 2) / N_;
    int b = bt / T_, t = bt % T_;
    const float4* src = (const float4*)(nodes_x + ((size_t)bt * N_ + n) * FN_ + q * 8);
    float4 a = src[0], c = src[1];
    union { __half2 h[4]; uint4 u; } cv;
    cv.h[0] = __floats2half2_rn(a.x, a.y);
    cv.h[1] = __floats2half2_rn(a.z, a.w);
    cv.h[2] = __floats2half2_rn(c.x, c.y);
    cv.h[3] = __floats2half2_rn(c.z, c.w);
    *(uint4*)&g_X[((size_t)(b * N_ + n)) * K_ + t * FN_ + q * 8] = cv.u;
}

// per-node segment mean of patch rows -> X[b*N+n][384 + t*32+fp] fp16 (one warp per node)
__global__ void k_mean(const float* __restrict__ patch) {
    int gw   = (blockIdx.x * blockDim.x + threadIdx.x) >> 5;
    int lane = threadIdx.x & 31;
    if (gw >= N_) return;
    int n    = gw;
    int base = g_off[n];
    int cnt  = g_off[n + 1] - base;
    float inv = 1.0f / fmaxf((float)cnt, 1.0f);
    int myp = 0;
    if (lane < cnt) myp = g_edgep[base + lane];
    int jmax = cnt < 32 ? cnt : 32;
    for (int bt = 0; bt < B_ * T_; ++bt) {
        float s = 0.0f;
        for (int j = 0; j < jmax; ++j) {
            int p = __shfl_sync(0xffffffffu, myp, j);
            s += patch[((size_t)bt * P_ + p) * FP_ + lane];
        }
        for (int j = 32; j < cnt; ++j) {           // pathological fan-in fallback
            int p = g_edgep[base + j];
            s += patch[((size_t)bt * P_ + p) * FP_ + lane];
        }
        int b = bt / T_, t = bt % T_;
        g_X[((size_t)(b * N_ + n)) * K_ + T_ * FN_ + t * FP_ + lane] = __float2half_rn(s * inv);
    }
}

// ---------------- mma.sync GEMM (legacy HMMA path; compute_103-safe) ----------------
__device__ __forceinline__ uint32_t smem_u32(const void* p) {
    uint32_t a;
    asm volatile("{ .reg .u64 t; cvta.to.shared.u64 t, %1; cvt.u32.u64 %0, t; }"
                 : "=r"(a) : "l"(p));
    return a;
}

__device__ __forceinline__ void ldsm4(uint32_t* r, uint32_t addr) {
    asm volatile("ldmatrix.sync.aligned.m8n8.x4.shared.b16 {%0,%1,%2,%3}, [%4];"
                 : "=r"(r[0]), "=r"(r[1]), "=r"(r[2]), "=r"(r[3]) : "r"(addr));
}

__device__ __forceinline__ void mma16816(float* c, const uint32_t* a,
                                         uint32_t b0, uint32_t b1) {
    asm volatile("mma.sync.aligned.m16n8k16.row.col.f32.f16.f16.f32 "
                 "{%0,%1,%2,%3}, {%4,%5,%6,%7}, {%8,%9}, {%0,%1,%2,%3};"
                 : "+f"(c[0]), "+f"(c[1]), "+f"(c[2]), "+f"(c[3])
                 : "r"(a[0]), "r"(a[1]), "r"(a[2]), "r"(a[3]), "r"(b0), "r"(b1));
}

#define CPASYNC16(dst, src) \
    asm volatile("cp.async.cg.shared.global [%0], [%1], 16;" :: "r"(dst), "l"(src))
#define CPCOMMIT() asm volatile("cp.async.commit_group;" ::: "memory")
#define CPWAIT1()  asm volatile("cp.async.wait_group 1;" ::: "memory")
#define CPWAIT0()  asm volatile("cp.async.wait_group 0;" ::: "memory")

// smem layout (bytes):
//   W2 @ 0        : 768*12*4 = 36864
//   b1 @ 36864    : 768*4    = 3072
//   tiles @ 40960 : 3 stages * (A 128*80 + B 128*80) = 3*20480 = 61440
//   reduce buffer reuses tile area after GEMM
#define SM_W2   0
#define SM_B1   36864
#define SM_TILE 40960
#define STAGE_BYTES 20480
#define ROW_PITCH   80
#define SMEM_BYTES  102400

__global__ void __launch_bounds__(256, 1)
k_gemm(const float* __restrict__ b1, const float* __restrict__ W2,
       const float* __restrict__ b2, float* __restrict__ out)
{
    extern __shared__ char smem[];
    const int tid   = threadIdx.x;
    const int lane  = tid & 31;
    const int wid   = tid >> 5;
    const int warpM = wid >> 1;          // 0..3
    const int warpN = wid & 1;           // 0..1
    const int m0    = blockIdx.x * 128;

    float* w2s = (float*)(smem + SM_W2);
    float* b1s = (float*)(smem + SM_B1);
    const uint32_t tile_base = smem_u32(smem + SM_TILE);

    for (int i = tid; i < K_ * H_; i += 256) w2s[i] = W2[i];
    for (int i = tid; i < K_;      i += 256) b1s[i] = b1[i];
    __syncthreads();

    // per-thread tile load coords: 512 16B chunks per operand tile, 2 per thread
    const int r0 = tid >> 2;             // rows handled: r0, r0+64
    const int c0 = tid & 3;              // 16B chunk within 64B row

    // persistent fused-GEMM2 output partials: 4 rows x 3 outputs
    float pers[4][3];
#pragma unroll
    for (int i = 0; i < 4; ++i)
#pragma unroll
        for (int j = 0; j < 3; ++j) pers[i][j] = 0.0f;

    float acc[2][8][4];

#pragma unroll 1
    for (int nt = 0; nt < 6; ++nt) {
        const int n0 = nt * 128;
#pragma unroll
        for (int mf = 0; mf < 2; ++mf)
#pragma unroll
            for (int nf = 0; nf < 8; ++nf)
#pragma unroll
                for (int q = 0; q < 4; ++q) acc[mf][nf][q] = 0.0f;

        // ---- prologue: stages 0,1 ----
#pragma unroll
        for (int s = 0; s < 2; ++s) {
            const int k0 = s * 32;
            uint32_t sA = tile_base + s * STAGE_BYTES;
            uint32_t sB = sA + 128 * ROW_PITCH;
#pragma unroll
            for (int it = 0; it < 2; ++it) {
                int r = r0 + it * 64;
                CPASYNC16(sA + r * ROW_PITCH + c0 * 16,
                          (const void*)&g_X[(size_t)(m0 + r) * K_ + k0 + c0 * 8]);
                CPASYNC16(sB + r * ROW_PITCH + c0 * 16,
                          (const void*)&g_W1t[(size_t)(n0 + r) * K_ + k0 + c0 * 8]);
            }
            CPCOMMIT();
        }

#pragma unroll 1
        for (int kt = 0; kt < 24; ++kt) {
            if (kt < 23) { CPWAIT1(); } else { CPWAIT0(); }
            __syncthreads();

            if (kt + 2 < 24) {
                const int k0 = (kt + 2) * 32;
                const int st = (kt + 2) % 3;
                uint32_t sA = tile_base + st * STAGE_BYTES;
                uint32_t sB = sA + 128 * ROW_PITCH;
#pragma unroll
                for (int it = 0; it < 2; ++it) {
                    int r = r0 + it * 64;
                    CPASYNC16(sA + r * ROW_PITCH + c0 * 16,
                              (const void*)&g_X[(size_t)(m0 + r) * K_ + k0 + c0 * 8]);
                    CPASYNC16(sB + r * ROW_PITCH + c0 * 16,
                              (const void*)&g_W1t[(size_t)(n0 + r) * K_ + k0 + c0 * 8]);
                }
                CPCOMMIT();
            }

            // ---- compute current stage ----
            const int st = kt % 3;
            uint32_t sA = tile_base + st * STAGE_BYTES;
            uint32_t sB = sA + 128 * ROW_PITCH;
#pragma unroll
            for (int ks = 0; ks < 2; ++ks) {
                uint32_t afr[2][4], bfr[4][4];
#pragma unroll
                for (int mf = 0; mf < 2; ++mf) {
                    uint32_t addr = sA + (warpM * 32 + mf * 16 + (lane & 15)) * ROW_PITCH
                                       + (ks * 2 + (lane >> 4)) * 16;
                    ldsm4(afr[mf], addr);
                }
#pragma unroll
                for (int nq = 0; nq < 4; ++nq) {
                    uint32_t addr = sB + (warpN * 64 + nq * 16 + (lane & 7) + ((lane >> 4) & 1) * 8) * ROW_PITCH
                                       + (ks * 2 + ((lane >> 3) & 1)) * 16;
                    ldsm4(bfr[nq], addr);
                }
#pragma unroll
                for (int mf = 0; mf < 2; ++mf)
#pragma unroll
                    for (int nq = 0; nq < 4; ++nq) {
                        mma16816(acc[mf][nq * 2],     afr[mf], bfr[nq][0], bfr[nq][1]);
                        mma16816(acc[mf][nq * 2 + 1], afr[mf], bfr[nq][2], bfr[nq][3]);
                    }
            }
        }

        // ---- epilogue: +b1, relu, fused GEMM2 into persistent partials ----
#pragma unroll
        for (int mf = 0; mf < 2; ++mf) {
#pragma unroll
            for (int hr = 0; hr < 2; ++hr) {
                float p[12];
#pragma unroll
                for (int o = 0; o < 12; ++o) p[o] = 0.0f;
#pragma unroll
                for (int nf = 0; nf < 8; ++nf) {
                    int col0 = n0 + warpN * 64 + nf * 8 + (lane & 3) * 2;
                    float v0 = fmaxf(acc[mf][nf][2 * hr]     + b1s[col0],     0.0f);
                    float v1 = fmaxf(acc[mf][nf][2 * hr + 1] + b1s[col0 + 1], 0.0f);
                    const float4* wp0 = (const float4*)(w2s + col0 * 12);
                    const float4* wp1 = (const float4*)(w2s + (col0 + 1) * 12);
                    float4 a0 = wp0[0], a1 = wp0[1], a2 = wp0[2];
                    float4 d0 = wp1[0], d1 = wp1[1], d2 = wp1[2];
                    p[0]  += v0 * a0.x + v1 * d0.x;  p[1]  += v0 * a0.y + v1 * d0.y;
                    p[2]  += v0 * a0.z + v1 * d0.z;  p[3]  += v0 * a0.w + v1 * d0.w;
                    p[4]  += v0 * a1.x + v1 * d1.x;  p[5]  += v0 * a1.y + v1 * d1.y;
                    p[6]  += v0 * a1.z + v1 * d1.z;  p[7]  += v0 * a1.w + v1 * d1.w;
                    p[8]  += v0 * a2.x + v1 * d2.x;  p[9]  += v0 * a2.y + v1 * d2.y;
                    p[10] += v0 * a2.z + v1 * d2.z;  p[11] += v0 * a2.w + v1 * d2.w;
                }
                // reduce across the quad (lanes sharing the same row)
#pragma unroll
                for (int o = 0; o < 12; ++o) {
                    p[o] += __shfl_xor_sync(0xffffffffu, p[o], 1);
                    p[o] += __shfl_xor_sync(0xffffffffu, p[o], 2);
                }
                int q = lane & 3;
                pers[mf * 2 + hr][0] += p[3 * q + 0];
                pers[mf * 2 + hr][1] += p[3 * q + 1];
                pers[mf * 2 + hr][2] += p[3 * q + 2];
            }
        }
        __syncthreads();   // before reloading tiles next nt
    }

    // ---- cross-warpN reduction through smem, then global write ----
    float* red = (float*)(smem + SM_TILE);  // [128][12] floats = 6144 B
    if (warpN == 1) {
#pragma unroll
        for (int i = 0; i < 4; ++i) {
            int mf = i >> 1, hr = i & 1;
            int rowL = warpM * 32 + mf * 16 + hr * 8 + (lane >> 2);
            int q = lane & 3;
#pragma unroll
            for (int j = 0; j < 3; ++j)
                red[rowL * 12 + 3 * q + j] = pers[i][j];
        }
    }
    __syncthreads();
    if (warpN == 0) {
#pragma unroll
        for (int i = 0; i < 4; ++i) {
            int mf = i >> 1, hr = i & 1;
            int rowL = warpM * 32 + mf * 16 + hr * 8 + (lane >> 2);
            int q = lane & 3;
            size_t row = (size_t)(m0 + rowL);
#pragma unroll
            for (int j = 0; j < 3; ++j) {
                int o = 3 * q + j;
                out[row * 12 + o] = pers[i][j] + red[rowL * 12 + o] + b2[o];
            }
        }
    }
}

// ---------------- launch ----------------
extern "C" void kernel_launch(void* const* d_in, const int* in_sizes, int n_in,
                              void* d_out, int out_size)
{
    const float* patch  = (const float*)d_in[0];
    const float* nodes  = (const float*)d_in[1];
    const int*   batch  = (const int*)d_in[2];
    const int*   mapper = (const int*)d_in[3];
    const float* W1     = (const float*)d_in[4];
    const float* b1     = (const float*)d_in[5];
    const float* W2     = (const float*)d_in[6];
    const float* b2     = (const float*)d_in[7];
    float*       out    = (float*)d_out;

    k_zero_cnt<<<(N_ + 255) / 256, 256>>>();
    k_hist<<<(E_ + 255) / 256, 256>>>(mapper);
    k_scan<<<1, 1024>>>();
    k_scatter<<<(E_ + 255) / 256, 256>>>(mapper, batch);
    k_w1t<<<(K_ * K_ + 255) / 256, 256>>>(W1);
    k_nx<<<(B_ * T_ * N_ * 4 + 255) / 256, 256>>>(nodes);
    k_mean<<<(N_ * 32 + 255) / 256, 256>>>(patch);

    cudaFuncSetAttribute(k_gemm, cudaFuncAttributeMaxDynamicSharedMemorySize, SMEM_BYTES);
    k_gemm<<<M_ / 128, 256, SMEM_BYTES>>>(b1, W2, b2, out);
}